// round 8
// baseline (speedup 1.0000x reference)
#include <cuda_runtime.h>
#include <cuda_bf16.h>

// Shapes (fixed): B=1, C=8, O=8, G=12, X=Y=Z=12, H=8, W=40, Bb=7 (basis), 27 taps
// x      : (1,8,12,12,12,8,40) f32   strides: c 552960, xi 46080, yi 3840, zi 320, h 40, w 1
// weight : (8,8,3,3,3,7)       f32
// bias   : (8,3,3,3)           f32
// basis  : (12,7,3,3)          f32
// out    : (1,96,12,12,12,8,40) f32
//
// Factored algorithm:
//   Y[b,o,h,w]   = sum_{c,f} x[c, n+f, h, w] * weight[o,c,f,b]          (per n)
//   out[g*8+o,.] = biasSum[o] + sum_{b,u,v} basis[(g+border)%12,b,u,v] * Y[b,o,hh0+u,ww0+v]
// One CTA per cell, NT=320, ~109KB smem, 2 CTAs/SM. All inner FMAs are fma.rn.f32x2.
// Weight planes streamed per-f from gmem pre-duplicated as (w,w) pairs.

#define NT 320
// smem floats: sWf[2*1024] + sBp[2016] + sBiasS[16] + sX[2*2560] + sY[56*320]
#define SMEM_FLOATS (2048 + 2016 + 16 + 5120 + 17920)
#define SMEM_BYTES (SMEM_FLOATS * 4)

typedef unsigned long long ull;

__device__ __forceinline__ void fma2(ull& d, ull a, ull b) {
    asm("fma.rn.f32x2 %0, %1, %2, %0;" : "+l"(d) : "l"(a), "l"(b));
}
__device__ __forceinline__ ull pack2(float lo, float hi) {
    ull r; asm("mov.b64 %0, {%1, %2};" : "=l"(r) : "f"(lo), "f"(hi)); return r;
}
__device__ __forceinline__ void unpack2(float& lo, float& hi, ull v) {
    asm("mov.b64 {%0, %1}, %2;" : "=f"(lo), "=f"(hi) : "l"(v));
}

__device__ float gW2[27 * 1024];    // [f][c][o][16]: (w,w) dup pairs over b, b==7 pad 0
__device__ float gBp[2 * 63 * 16];  // [shift][kk][g(12, pad 16)]: pre-rotated basis
__device__ float gBiasS[8];

// zero_shell + one-shot prep (first blocks also build gW2/gBp/gBiasS).
__global__ __launch_bounds__(512)
void zero_prep(const float* __restrict__ weight,
               const float* __restrict__ bias,
               const float* __restrict__ basis,
               float* __restrict__ out)
{
    const int blk = blockIdx.x, tid = threadIdx.x;

    if (blk < 54) {               // 54*512 = 27648 = gW2 elements
        int idx = blk * 512 + tid;
        int f   = idx >> 10;
        int rem = idx & 1023;
        int c   = rem >> 7;
        int col = rem & 127;
        int o   = col >> 4;
        int b   = (col & 15) >> 1;    // dup-pair index
        gW2[idx] = (b < 7) ? weight[o * 1512 + c * 189 + f * 7 + b] : 0.f;
    } else if (blk == 54) {
        if (tid < 8) {
            float s = 0.f;
            #pragma unroll
            for (int t = 0; t < 27; t++) s += bias[tid * 27 + t];
            gBiasS[tid] = s;
        }
        for (int i = tid; i < 2016; i += 512) {
            int s  = i / 1008;
            int kk = (i % 1008) >> 4;
            int g  = i & 15;
            int ge = g + s; if (ge >= 12) ge -= 12;
            gBp[i] = (g < 12) ? basis[ge * 63 + kk] : 0.f;
        }
    }

    // shell zeroing: one thread = one float4 slot; interior skipped
    const int idx   = blk * 512 + tid;
    const int cellE = idx / 80;
    const int s4    = idx % 80;
    const int go    = cellE / 1728;
    const int cell  = cellE % 1728;
    const int cx = cell / 144, cy = (cell / 12) % 12, cz = cell % 12;
    if (cx >= 1 && cx <= 9 && cy >= 1 && cy <= 9 && cz >= 1 && cz <= 9) return;
    reinterpret_cast<float4*>(out + (size_t)go * 552960 + (size_t)cell * 320)[s4] =
        make_float4(0.f, 0.f, 0.f, 0.f);
}

__global__ __launch_bounds__(NT, 2)
void gconv_main(const float* __restrict__ x, float* __restrict__ out)
{
    extern __shared__ float smem[];
    float* sWf    = smem;            // [2][1024] double-buffered dup weight plane
    float* sBp    = sWf + 2048;      // [2][63][16]
    float* sBiasS = sBp + 2016;      // [8] (+8 pad)
    float* sX     = sBiasS + 16;     // [2][8][320] double-buffered x plane
    float* sY     = sX + 5120;       // [56][320]   (o*7+b) x pix

    const int tid  = threadIdx.x;
    const int cell = blockIdx.x;
    const int xi = cell / 81, yi = (cell / 9) % 9, zi = cell % 9;

    // ---- stage small constants ----
    {
        float4* b4 = reinterpret_cast<float4*>(sBp);
        const float4* gb4 = reinterpret_cast<const float4*>(gBp);
        for (int i = tid; i < 504; i += NT) b4[i] = gb4[i];
        if (tid < 8) sBiasS[tid] = gBiasS[tid];
    }

    // ---- Phase 1: Y[o*7+b][pix]; thread = (o-pair op, 4 consecutive px) ----
    const int op  = tid / 80;          // 0..3 -> o in {2op, 2op+1}
    const int t_q = tid % 80;          // px 4*t_q .. 4*t_q+3

    ull acc2[2][7][2];
    #pragma unroll
    for (int t = 0; t < 2; t++)
        #pragma unroll
        for (int i = 0; i < 7; i++) { acc2[t][i][0] = 0ULL; acc2[t][i][1] = 0ULL; }

    const float* xn = x + (size_t)xi * 46080 + (size_t)yi * 3840 + (size_t)zi * 320;
    const float4* gW4 = reinterpret_cast<const float4*>(gW2);

    // staging roles: x plane 640 float4 (2/thread); weight plane 256 float4 (tid<256)
    const int cA0 = tid / 80,         pA0 = tid % 80;
    const int cA1 = (tid + 320) / 80, pA1 = (tid + 320) % 80;

    float4 preX0, preX1, preW;
    {
        const float4* xb4 = reinterpret_cast<const float4*>(xn);
        preX0 = xb4[(size_t)cA0 * 138240 + pA0];
        preX1 = xb4[(size_t)cA1 * 138240 + pA1];
        if (tid < 256) preW = gW4[tid];
    }

    for (int f = 0; f < 27; f++) {
        const int buf = f & 1;
        reinterpret_cast<float4*>(sX + buf * 2560)[cA0 * 80 + pA0] = preX0;
        reinterpret_cast<float4*>(sX + buf * 2560)[cA1 * 80 + pA1] = preX1;
        if (tid < 256)
            reinterpret_cast<float4*>(sWf + buf * 1024)[tid] = preW;
        if (f < 26) {
            const int fn = f + 1;
            const int fi = fn / 9, fj = (fn / 3) % 3, fk = fn % 3;
            const float4* xb4 = reinterpret_cast<const float4*>(
                xn + fi * 46080 + fj * 3840 + fk * 320);
            preX0 = xb4[(size_t)cA0 * 138240 + pA0];
            preX1 = xb4[(size_t)cA1 * 138240 + pA1];
            if (tid < 256) preW = gW4[fn * 256 + tid];
        }
        __syncthreads();
        const float* xs = sX + buf * 2560;
        const float* wf = sWf + buf * 1024;
        #pragma unroll
        for (int c = 0; c < 8; c++) {
            ulonglong2 xv = *reinterpret_cast<const ulonglong2*>(xs + c * 320 + t_q * 4);
            #pragma unroll
            for (int t = 0; t < 2; t++) {
                const ulonglong2* wp = reinterpret_cast<const ulonglong2*>(
                    wf + c * 128 + (op * 2 + t) * 16);
                ulonglong2 wA = wp[0];   // dup pairs b0,b1
                ulonglong2 wB = wp[1];   // b2,b3
                ulonglong2 wC = wp[2];   // b4,b5
                ulonglong2 wD = wp[3];   // b6,(pad)
                fma2(acc2[t][0][0], wA.x, xv.x); fma2(acc2[t][0][1], wA.x, xv.y);
                fma2(acc2[t][1][0], wA.y, xv.x); fma2(acc2[t][1][1], wA.y, xv.y);
                fma2(acc2[t][2][0], wB.x, xv.x); fma2(acc2[t][2][1], wB.x, xv.y);
                fma2(acc2[t][3][0], wB.y, xv.x); fma2(acc2[t][3][1], wB.y, xv.y);
                fma2(acc2[t][4][0], wC.x, xv.x); fma2(acc2[t][4][1], wC.x, xv.y);
                fma2(acc2[t][5][0], wC.y, xv.x); fma2(acc2[t][5][1], wC.y, xv.y);
                fma2(acc2[t][6][0], wD.x, xv.x); fma2(acc2[t][6][1], wD.x, xv.y);
            }
        }
    }
    __syncthreads();
    #pragma unroll
    for (int t = 0; t < 2; t++)
        #pragma unroll
        for (int i = 0; i < 7; i++) {
            ulonglong2 v; v.x = acc2[t][i][0]; v.y = acc2[t][i][1];
            *reinterpret_cast<ulonglong2*>(sY + ((op * 2 + t) * 7 + i) * 320 + t_q * 4) = v;
        }
    __syncthreads();

    // ---- Phase 2: thread = pixel; two passes over o-halves, 12 g (6 pairs) x 4 o ----
    const int h = tid / 40, w = tid % 40;
    const int hh0 = min(max(h, 1), 6) - 1;
    const int ww0 = min(max(w, 1), 38) - 1;
    const int bshift = ((h == 0) | (h == 7) | (w == 0) | (w == 39)) ? 1 : 0;
    const float* bas = sBp + bshift * 1008;   // [63][16] pre-rotated

    for (int pass = 0; pass < 2; pass++) {
        ull accP[6][4];
        #pragma unroll
        for (int o = 0; o < 4; o++) {
            float bs = sBiasS[pass * 4 + o];
            ull bp = pack2(bs, bs);
            #pragma unroll
            for (int k = 0; k < 6; k++) accP[k][o] = bp;
        }

        const int ybase = pass * 4 * 7 * 320;
        for (int b = 0; b < 7; b++) {
            #pragma unroll
            for (int u = 0; u < 3; u++) {
                #pragma unroll
                for (int v = 0; v < 3; v++) {
                    const int kk = b * 9 + u * 3 + v;
                    const int yoff = (hh0 + u) * 40 + (ww0 + v);
                    ull yd[4];
                    #pragma unroll
                    for (int o = 0; o < 4; o++) {
                        float yv = sY[ybase + (o * 7 + b) * 320 + yoff];
                        yd[o] = pack2(yv, yv);
                    }
                    const ulonglong2* bp = reinterpret_cast<const ulonglong2*>(bas + kk * 16);
                    ulonglong2 b01 = bp[0];   // g-pairs (0,1),(2,3)
                    ulonglong2 b23 = bp[1];   // (4,5),(6,7)
                    ulonglong2 b45 = bp[2];   // (8,9),(10,11)
                    #pragma unroll
                    for (int o = 0; o < 4; o++) {
                        fma2(accP[0][o], b01.x, yd[o]);
                        fma2(accP[1][o], b01.y, yd[o]);
                        fma2(accP[2][o], b23.x, yd[o]);
                        fma2(accP[3][o], b23.y, yd[o]);
                        fma2(accP[4][o], b45.x, yd[o]);
                        fma2(accP[5][o], b45.y, yd[o]);
                    }
                }
            }
        }

        // ---- store: out[(2k+e)*8 + pass*4 + o, xi+1, yi+1, zi+1, px] ----
        float* ob = out + (size_t)(xi + 1) * 46080 + (size_t)(yi + 1) * 3840
                        + (size_t)(zi + 1) * 320 + tid + (size_t)pass * 4 * 552960;
        #pragma unroll
        for (int k = 0; k < 6; k++)
            #pragma unroll
            for (int o = 0; o < 4; o++) {
                float lo, hi;
                unpack2(lo, hi, accP[k][o]);
                ob[(size_t)((2 * k) * 8 + o) * 552960]     = lo;
                ob[(size_t)((2 * k + 1) * 8 + o) * 552960] = hi;
            }
    }
}

extern "C" void kernel_launch(void* const* d_in, const int* in_sizes, int n_in,
                              void* d_out, int out_size)
{
    const float* x      = (const float*)d_in[0];
    const float* weight = (const float*)d_in[1];
    const float* bias   = (const float*)d_in[2];
    const float* basis  = (const float*)d_in[3];
    // d_in[4..7] = I, J, T, bias_basis: deterministic clip/border maps, computed inline.
    float* out = (float*)d_out;

    cudaFuncSetAttribute(gconv_main, cudaFuncAttributeMaxDynamicSharedMemorySize, SMEM_BYTES);

    zero_prep<<<25920, 512>>>(weight, bias, basis, out);
    gconv_main<<<729, NT, SMEM_BYTES>>>(x, out);
}